// round 2
// baseline (speedup 1.0000x reference)
#include <cuda_runtime.h>
#include <cuda_bf16.h>

#define T_ 1024
#define B_ 64
#define C_ 512
#define U_ 128
#define STRIDE_ (B_*C_)

// scratch for per-batch losses (no cudaMalloc allowed)
__device__ float g_losses[B_];

// softmin2(x,y) = -TAU * log(exp(-x/TAU)+exp(-y/TAU)),  TAU=0.2
// = m - TAU*ln2 * log2(1 + 2^((m-M)/(TAU*ln2)))
__device__ __forceinline__ float softmin2(float x, float y) {
    float m = fminf(x, y);
    float M = fmaxf(x, y);
    float e = exp2f((m - M) * 7.2134752f);            // 1/(TAU*ln2); -> MUFU.EX2
    return fmaf(-0.13862944f, __log2f(1.0f + e), m);  // TAU*ln2
}

__global__ void __launch_bounds__(128, 1)
softper_dp_kernel(const float* __restrict__ lp,
                  const int*   __restrict__ targets,
                  const int*   __restrict__ in_len,
                  const int*   __restrict__ tg_len)
{
    const int b    = blockIdx.x;
    const int u    = threadIdx.x;      // target row index - 1, 0..127
    const int lane = u & 31;
    const int warp = u >> 5;

    // per-batch target offset (cumsum - len); 64 cached broadcast loads
    int off = 0;
    for (int i = 0; i < b; ++i) off += __ldg(&tg_len[i]);
    int tl = __ldg(&tg_len[b]); tl = max(1, min(tl, U_));
    int il = __ldg(&in_len[b]); il = max(1, min(il, T_));

    int idx = min(max(off + u, 0), B_*U_ - 1);
    int cu  = (u < tl) ? __ldg(&targets[idx]) : 0;  // BLANK_ID = 0
    cu = min(max(cu, 0), C_ - 1);
    const float* col = lp + (size_t)b * C_ + cu;    // + t*STRIDE_ for time t

    const int r = u + 1;                 // my DP row
    float prev_self = (float)r;          // D[0][r] = r*DEL
    float nb_prev   = (float)u;          // D[0][r-1]

    __shared__ float sbuf[2][4];         // warp-boundary exchange, double buffered
    if (lane == 31) sbuf[0][warp] = prev_self;
    __syncthreads();

    const int S       = il + tl;         // last diagonal (cell (il, tl))
    const int nsteps  = S - 1;           // steps s = 2..S
    const int nblocks = (nsteps + 3) >> 2;

    // prefetch ring: block k covers steps s=2+4k..5+4k, needs t = 4k - u + z
    float q[2][4];
    #pragma unroll
    for (int z = 0; z < 4; ++z) {
        int t0 = max(0, min(0 * 4 - u + z, T_ - 1));
        int t1 = max(0, min(1 * 4 - u + z, T_ - 1));
        q[0][z] = __ldg(col + (size_t)t0 * STRIDE_);
        q[1][z] = __ldg(col + (size_t)t1 * STRIDE_);
    }

    for (int k = 0; k < nblocks; ++k) {
        const int qc = k & 1;
        float p0 = q[qc][0], p1 = q[qc][1], p2 = q[qc][2], p3 = q[qc][3];

        // prefetch block k+2 (same parity slot, ~8 steps of latency cover)
        {
            int tb = (k + 2) * 4 - u;
            #pragma unroll
            for (int z = 0; z < 4; ++z) {
                int t = max(0, min(tb + z, T_ - 1));
                q[qc][z] = __ldg(col + (size_t)t * STRIDE_);
            }
        }

        const int s0 = 2 + k * 4;
        #pragma unroll
        for (int z = 0; z < 4; ++z) {
            const int s  = s0 + z;
            float pv = (z == 0) ? p0 : (z == 1) ? p1 : (z == 2) ? p2 : p3;

            // neighbor's D[j][r-1] (computed by thread u-1 last step)
            float nb = __shfl_up_sync(0xffffffffu, prev_self, 1);
            if (lane == 0)
                nb = (warp == 0) ? (float)(s - 1)         // row 0: D[j][0] = j*INS, j=s-1
                                 : sbuf[s & 1][warp - 1];

            const int j = s - r;
            float sub = 1.0f - __expf(pv);                // 1 - p_correct
            // softmin3 via associativity; partial overlaps shfl latency
            float partial = softmin2(prev_self + 1.0f,    // D[j-1][r]   + INS
                                     nb_prev   + sub);    // D[j-1][r-1] + sub
            float val     = softmin2(partial, nb + 1.0f); // D[j][r-1]   + DEL

            nb_prev = nb;
            bool act = (j >= 1) & (j <= il) & (r <= tl);
            if (act) prev_self = val;

            if (lane == 31) sbuf[(s + 1) & 1][warp] = prev_self;
            __syncthreads();
        }
    }

    if (u == tl - 1)
        g_losses[b] = prev_self / ((float)tl + 1e-8f);
}

__global__ void softper_reduce_kernel(float* __restrict__ out)
{
    __shared__ float sh[2];
    int t = threadIdx.x;               // 64 threads
    float v = g_losses[t];
    #pragma unroll
    for (int o = 16; o > 0; o >>= 1)
        v += __shfl_down_sync(0xffffffffu, v, o);
    if ((t & 31) == 0) sh[t >> 5] = v;
    __syncthreads();
    if (t == 0) out[0] = (sh[0] + sh[1]) * (1.0f / (float)B_);
}

extern "C" void kernel_launch(void* const* d_in, const int* in_sizes, int n_in,
                              void* d_out, int out_size)
{
    const float* lp      = (const float*)d_in[0];
    const int*   targets = (const int*)  d_in[1];
    const int*   in_len  = (const int*)  d_in[2];
    const int*   tg_len  = (const int*)  d_in[3];

    softper_dp_kernel<<<B_, 128>>>(lp, targets, in_len, tg_len);
    softper_reduce_kernel<<<1, 64>>>((float*)d_out);
}

// round 3
// speedup vs baseline: 1.3631x; 1.3631x over previous
#include <cuda_runtime.h>
#include <cuda_bf16.h>

#define T_ 1024
#define B_ 64
#define C_ 512
#define U_ 128
#define STRIDE_ (B_*C_)

__device__ float g_losses[B_];
__device__ unsigned int g_done;   // zero-initialized; last CTA resets to 0

// constants
#define KD_     0.006737946999085467f   // exp(-5) = exp(-DEL/tau), also INS
#define LOG2E_  1.4426950408889634f
#define ITL2_   7.213475204444817f      // 1/(tau*ln2) = 5*log2(e)
#define TL2_    0.13862943611198906f    // tau*ln2
#define E20_    4.851651954097903e8f    // exp(20)  (initial inter-thread scale)
#define E5_     148.4131591025766f      // exp(5)

__global__ void __launch_bounds__(32, 1)
softper_exp_kernel(const float* __restrict__ lp,
                   const int*   __restrict__ targets,
                   const int*   __restrict__ in_len,
                   const int*   __restrict__ tg_len,
                   float*       __restrict__ out)
{
    const int b = blockIdx.x;
    const int t = threadIdx.x;          // 32 threads; thread t owns rows 4t+1..4t+4
    const bool l0 = (t == 0);

    // per-batch target offset (cumsum - len)
    int off = 0;
    for (int i = 0; i < b; ++i) off += __ldg(&tg_len[i]);
    int tl = min(max(__ldg(&tg_len[b]), 1), U_);
    int il = min(max(__ldg(&in_len[b]),  1), T_);
    const int tstar = (tl - 1) >> 2;
    const int mstar = (tl - 1) & 3;

    // gather column base pointers for my 4 rows
    const float* base[4];
    #pragma unroll
    for (int m = 0; m < 4; ++m) {
        int u = 4*t + m;
        int idx = min(max(off + u, 0), B_*U_ - 1);
        int cu = (u < tl) ? __ldg(&targets[idx]) : 0;   // BLANK_ID=0
        cu = min(max(cu, 0), C_ - 1);
        base[m] = lp + b * C_ + cu;
    }

    // state: F = exp(-(D - C)/tau), C = 4t+1 initially; L = C/(tau*ln2)
    float E[4] = {1.0f, 0.006737947f, 4.5399930e-05f, 3.0590232e-07f}; // e^{-5m}
    float Lofs = (float)(4*t + 1) * ITL2_;
    float bndA = E5_;                    // lane0: E(0,0)=exp(-(0-1)/tau)=e^5 (own scale)
    float cS   = l0 ? KD_ : KD_ * E20_;  // e^{-5} * exp((C_t - C_{t-1})/tau); C diff = 4

    // neighbor pipeline: nbA = E(j,4t), nbB = E(j-1,4t) in neighbor's scale
    float nbA = __shfl_up_sync(0xffffffffu, E[3], 1);
    float nbB = nbA;

    // prefetch ring: 8 step-quads ahead. step s uses time tt = s - t - 1
    float q[8][4];
    #pragma unroll
    for (int z = 0; z < 8; ++z) {
        int tt = min(max(z - t, 0), T_ - 1);
        size_t o = (size_t)tt * STRIDE_;
        #pragma unroll
        for (int m = 0; m < 4; ++m) q[z][m] = __ldg(base[m] + o);
    }

    const int S_end   = il + tstar;          // last step we need
    const int nblocks = (S_end + 7) >> 3;

    for (int k = 0; k < nblocks; ++k) {
        #pragma unroll
        for (int z = 0; z < 8; ++z) {
            const int s = 8*k + z + 1;
            const int j = s - t;
            const bool act = (j >= 1) & (j <= il);

            // lane0 boundary column: E(j,0) = exp(-(min(j,il) - C)/tau)
            float bnd_old = bndA;
            if (l0 && act) bndA *= KD_;
            float lft   = l0 ? bndA    : nbA;   // E(j,   r-1) for m=0
            float lprev = l0 ? bnd_old : nbB;   // E(j-1, r-1) for m=0

            #pragma unroll
            for (int m = 0; m < 4; ++m) {
                float p   = exp2f(LOG2E_ * q[z][m]);   // exp(lp)
                float ex  = exp2f(ITL2_  * p);         // exp(5p)
                float kdm = (m == 0) ? cS : KD_;       // scale-adjusted for neighbor
                float ks  = kdm * ex;
                float h   = fmaf(KD_, E[m], ks * lprev);
                float en  = fmaf(kdm, lft, h);
                lprev = E[m];                  // old value = E(j-1, r) for next row's diag
                if (act) E[m] = en;
                lft = E[m];                    // E(j, r) for next row's left
            }

            // prefetch quad for step s+8 into the slot just consumed
            {
                int tt = min(max(s + 7 - t, 0), T_ - 1);
                size_t o = (size_t)tt * STRIDE_;
                #pragma unroll
                for (int m = 0; m < 4; ++m) q[z][m] = __ldg(base[m] + o);
            }

            // extract final cell D(il, tl)
            if ((t == tstar) && (j == il)) {
                float Ev = (mstar == 0) ? E[0] : (mstar == 1) ? E[1]
                         : (mstar == 2) ? E[2] : E[3];
                float D = TL2_ * (Lofs - __log2f(Ev));
                g_losses[b] = D / ((float)tl + 1e-8f);
            }

            // pass my last row to the right neighbor
            nbB = nbA;
            nbA = __shfl_up_sync(0xffffffffu, E[3], 1);

            // renormalize every 4 steps (keeps F in float range, bounds S)
            if ((z & 3) == 3) {
                float M = fmaxf(fmaxf(E[0], E[1]), fmaxf(E[2], E[3]));
                if (l0) M = fmaxf(M, bndA);
                M = fmaxf(M, 1e-30f);
                float rinv = 1.0f / M;
                E[0] *= rinv; E[1] *= rinv; E[2] *= rinv; E[3] *= rinv;
                if (l0) bndA *= rinv;
                Lofs -= __log2f(M);            // C_new = C - tau*ln(M)
                float rnb = __shfl_up_sync(0xffffffffu, rinv, 1);
                nbA *= rnb; nbB *= rnb;        // keep neighbor values in their new scale
                float Lnb = __shfl_up_sync(0xffffffffu, Lofs, 1);
                float Sn  = exp2f(Lofs - Lnb); // exp((C_t - C_nb)/tau)
                cS = l0 ? KD_ : KD_ * Sn;
            }
        }
    }

    // fold the mean-reduction into this kernel: last CTA to finish reduces
    __threadfence();
    unsigned lastf = 0;
    if (t == 0) lastf = (atomicAdd(&g_done, 1u) == B_ - 1) ? 1u : 0u;
    lastf = __shfl_sync(0xffffffffu, lastf, 0);
    if (lastf) {
        __threadfence();
        volatile float* gl = g_losses;
        float v = gl[t] + gl[t + 32];
        #pragma unroll
        for (int o2 = 16; o2 > 0; o2 >>= 1)
            v += __shfl_down_sync(0xffffffffu, v, o2);
        if (t == 0) { out[0] = v * (1.0f / (float)B_); g_done = 0; }
    }
}

extern "C" void kernel_launch(void* const* d_in, const int* in_sizes, int n_in,
                              void* d_out, int out_size)
{
    const float* lp      = (const float*)d_in[0];
    const int*   targets = (const int*)  d_in[1];
    const int*   in_len  = (const int*)  d_in[2];
    const int*   tg_len  = (const int*)  d_in[3];

    softper_exp_kernel<<<B_, 32>>>(lp, targets, in_len, tg_len, (float*)d_out);
}